// round 13
// baseline (speedup 1.0000x reference)
#include <cuda_runtime.h>

// Problem constants (fixed by the reference)
#define TABLE  16777216
#define RAYS   32768
#define NS     128      // samples per ray
#define IN_DIR 16
#define HID    8

// Inputs (metadata order):
//  d_in[0] x          int32  [B, N, 2]
//  d_in[1] d          float  [B, 16]
//  d_in[2] gridWeight float  [16777216, 4]
//  d_in[3] W0         float  [22, 8]
//  d_in[4] W1         float  [8, 3]
// Output: sigma [B, N] then rgb [B, 3], concatenated, float32.
//
// Model (R1-R11): uint8 table (64MB, L2-resident after convert's
// write-allocate) + constant W0 + warp-per-ray. surf sits on the ~33us
// irreducible L1tex gather-wavefront floor; convert sits on its 320MB
// streaming floor (~40us). R12 removes the R11 prep-kernel/cW1s copy chain
// (3.5us serialized) by folding 1/255 into the color sigmoid argument
// (3 FMUL/sample, hidden under the floor).

__device__ unsigned int g_q[TABLE];     // 64 MB: 4 x uint8 per row

__constant__ float cW0[22 * HID];       // raw W0 [22,8] row-major
__constant__ float cW1[HID * 3];        // raw W1 [8,3]  row-major

#define MAGIC_U  0x4B000000u            // float bits of 8388608.0f
#define MAGIC_F  8388608.f
#define INV65025 (1.f / 65025.f)
#define INV255   (1.f / 255.f)

// ---------------- Kernel A: fp32 -> uint8 table quantization ----------------
__device__ __forceinline__ unsigned int pack_row(float4 v) {
    unsigned int a = __float2uint_rn(v.x * 255.f);
    unsigned int b = __float2uint_rn(v.y * 255.f);
    unsigned int c = __float2uint_rn(v.z * 255.f);
    unsigned int d = __float2uint_rn(v.w * 255.f);
    return a | (b << 8) | (c << 16) | (d << 24);
}

__global__ __launch_bounds__(256) void convert_kernel(const float4* __restrict__ grid) {
    const int t    = blockIdx.x * blockDim.x + threadIdx.x;   // TABLE/4 threads
    const int base = t * 4;
    const float4 r0 = __ldcs(grid + base);
    const float4 r1 = __ldcs(grid + base + 1);
    const float4 r2 = __ldcs(grid + base + 2);
    const float4 r3 = __ldcs(grid + base + 3);
    uint4 o;
    o.x = pack_row(r0);
    o.y = pack_row(r1);
    o.z = pack_row(r2);
    o.w = pack_row(r3);
    *(((uint4*)g_q) + t) = o;   // normal store: write-allocate keeps table in L2
}

// ---------------- Kernel B: warp-per-ray gather + MLP + scan + reduce ----------------
__global__ __launch_bounds__(128) void surf_kernel(
    const uint4* __restrict__ x4,       // x as uint4 (4 ints = 2 sample pairs)
    const float* __restrict__ d,        // [B,16]
    float* __restrict__ out_sigma,      // [B,N]
    float* __restrict__ out_rgb)        // [B,3]
{
    const int ray  = blockIdx.x * 4 + (threadIdx.x >> 5);
    const int lane = threadIdx.x & 31;

    // ---- indices: samples lane*4 .. lane*4+3 -> 8 ints = 2 x LDG.128, coalesced ----
    const uint4* xp = x4 + (size_t)ray * (NS * 2 / 4) + lane * 2;
    const uint4 xa = __ldcs(xp);
    const uint4 xb = __ldcs(xp + 1);

    // ---- 8 independent gathers, issued back-to-back (L2-resident table) ----
    unsigned int q0[4], q1[4];
    q0[0] = __ldcg(&g_q[xa.x]);  q1[0] = __ldcg(&g_q[xa.y]);
    q0[1] = __ldcg(&g_q[xa.z]);  q1[1] = __ldcg(&g_q[xa.w]);
    q0[2] = __ldcg(&g_q[xb.x]);  q1[2] = __ldcg(&g_q[xb.y]);
    q0[3] = __ldcg(&g_q[xb.z]);  q1[3] = __ldcg(&g_q[xb.w]);

    // ---- per-ray base = 255 * (d-row @ W0[0:16]); lane computes j=lane&7 ----
    float basev = 0.f;
    {
        const int j = lane & 7;
        const float4* dd = (const float4*)(d + (size_t)ray * IN_DIR);
        #pragma unroll
        for (int k4 = 0; k4 < 4; ++k4) {
            const float4 dv = __ldg(dd + k4);
            basev = fmaf(dv.x, cW0[(k4 * 4 + 0) * HID + j], basev);
            basev = fmaf(dv.y, cW0[(k4 * 4 + 1) * HID + j], basev);
            basev = fmaf(dv.z, cW0[(k4 * 4 + 2) * HID + j], basev);
            basev = fmaf(dv.w, cW0[(k4 * 4 + 3) * HID + j], basev);
        }
        basev *= 255.f;     // layer0 runs on raw bytes; /255 folded into sigmoid arg
    }
    float base[HID];
    #pragma unroll
    for (int j = 0; j < HID; ++j)
        base[j] = __shfl_sync(0xffffffffu, basev, j);

    // ---- per-sample: sigma + tiny MLP ----
    float sig[4], cr[4], cg[4], cb[4];
    #pragma unroll
    for (int k = 0; k < 4; ++k) {
        const unsigned int a = q0[k], b = q1[k];

        // sigma: prod+MAGIC via one IMAD; one FMA gives -z; fast sigmoid
        const unsigned int pm = (a & 255u) * (b & 255u) + MAGIC_U;
        const float fp   = __uint_as_float(pm);                  // 8388608 + prod
        const float zneg = fmaf(fp, -INV65025, MAGIC_F * INV65025);
        sig[k] = __fdividef(1.f, 1.f + __expf(zneg));

        // geo bytes as exact small floats: PRMT + FSUB (no cvt, no scale)
        const float g0y = __uint_as_float(__byte_perm(a, MAGIC_U, 0x7441)) - MAGIC_F;
        const float g0z = __uint_as_float(__byte_perm(a, MAGIC_U, 0x7442)) - MAGIC_F;
        const float g0w = __uint_as_float(__byte_perm(a, MAGIC_U, 0x7443)) - MAGIC_F;
        const float g1y = __uint_as_float(__byte_perm(b, MAGIC_U, 0x7441)) - MAGIC_F;
        const float g1z = __uint_as_float(__byte_perm(b, MAGIC_U, 0x7442)) - MAGIC_F;
        const float g1w = __uint_as_float(__byte_perm(b, MAGIC_U, 0x7443)) - MAGIC_F;

        float h[HID];
        #pragma unroll
        for (int j = 0; j < HID; ++j) {
            float acc = base[j];
            acc = fmaf(g0y, cW0[(16 + 0) * HID + j], acc);
            acc = fmaf(g0z, cW0[(16 + 1) * HID + j], acc);
            acc = fmaf(g0w, cW0[(16 + 2) * HID + j], acc);
            acc = fmaf(g1y, cW0[(16 + 3) * HID + j], acc);
            acc = fmaf(g1z, cW0[(16 + 4) * HID + j], acc);
            acc = fmaf(g1w, cW0[(16 + 5) * HID + j], acc);
            h[j] = fmaxf(acc, 0.f);     // = 255 * true hidden
        }
        float c0 = 0.f, c1 = 0.f, c2 = 0.f;
        #pragma unroll
        for (int j = 0; j < HID; ++j) {
            c0 = fmaf(h[j], cW1[j * 3 + 0], c0);
            c1 = fmaf(h[j], cW1[j * 3 + 1], c1);
            c2 = fmaf(h[j], cW1[j * 3 + 2], c2);
        }
        // /255 folded here (scale of h) — one FMUL per channel
        cr[k] = __fdividef(1.f, 1.f + __expf(-c0 * INV255));
        cg[k] = __fdividef(1.f, 1.f + __expf(-c1 * INV255));
        cb[k] = __fdividef(1.f, 1.f + __expf(-c2 * INV255));
    }

    // ---- sigma out: one coalesced STG.128 per thread ----
    float4 s4 = make_float4(sig[0], sig[1], sig[2], sig[3]);
    __stcs((float4*)(out_sigma + (size_t)ray * NS) + lane, s4);

    // ---- exclusive prefix product of (1-sigma): local x warp-scan ----
    const float p0 = 1.f - sig[0];
    const float p1 = 1.f - sig[1];
    const float p2 = 1.f - sig[2];
    const float p3 = 1.f - sig[3];
    const float l1 = p0 * p1;            // local inclusive prefixes
    const float l2 = l1 * p2;
    const float ltot = l2 * p3;

    float incl = ltot;                   // warp inclusive scan of thread totals
    #pragma unroll
    for (int off = 1; off < 32; off <<= 1) {
        float v = __shfl_up_sync(0xffffffffu, incl, off);
        if (lane >= off) incl *= v;
    }
    float excl = __shfl_up_sync(0xffffffffu, incl, 1);   // exclusive
    if (lane == 0) excl = 1.f;

    const float w0 = excl      * sig[0];
    const float w1 = excl * p0 * sig[1];
    const float w2 = excl * l1 * sig[2];
    const float w3 = excl * l2 * sig[3];

    // ---- rgb = sum w*c : local accumulate then one warp butterfly ----
    float r = fmaf(w3, cr[3], fmaf(w2, cr[2], fmaf(w1, cr[1], w0 * cr[0])));
    float g = fmaf(w3, cg[3], fmaf(w2, cg[2], fmaf(w1, cg[1], w0 * cg[0])));
    float bl= fmaf(w3, cb[3], fmaf(w2, cb[2], fmaf(w1, cb[1], w0 * cb[0])));
    #pragma unroll
    for (int off = 16; off > 0; off >>= 1) {
        r  += __shfl_down_sync(0xffffffffu, r,  off);
        g  += __shfl_down_sync(0xffffffffu, g,  off);
        bl += __shfl_down_sync(0xffffffffu, bl, off);
    }
    if (lane == 0) {
        float* o = out_rgb + (size_t)ray * 3;
        o[0] = r; o[1] = g; o[2] = bl;
    }
}

extern "C" void kernel_launch(void* const* d_in, const int* in_sizes, int n_in,
                              void* d_out, int out_size) {
    const uint4* x4   = (const uint4*)d_in[0];
    const float* d    = (const float*)d_in[1];
    const float4* gw  = (const float4*)d_in[2];
    float* out_sigma  = (float*)d_out;
    float* out_rgb    = out_sigma + (size_t)RAYS * NS;

    // weights -> constant bank (D2D async memcpy: graph-capturable, no alloc);
    // issued first so they hide under convert.
    cudaMemcpyToSymbolAsync(cW0, d_in[3], 22 * HID * sizeof(float), 0,
                            cudaMemcpyDeviceToDevice);
    cudaMemcpyToSymbolAsync(cW1, d_in[4], HID * 3 * sizeof(float), 0,
                            cudaMemcpyDeviceToDevice);

    convert_kernel<<<TABLE / 4 / 256, 256>>>(gw);
    surf_kernel<<<RAYS / 4, 128>>>(x4, d, out_sigma, out_rgb);
}

// round 14
// speedup vs baseline: 1.0316x; 1.0316x over previous
#include <cuda_runtime.h>

// Problem constants (fixed by the reference)
#define TABLE  16777216
#define RAYS   32768
#define NS     128      // samples per ray
#define IN_DIR 16
#define HID    8

// Inputs (metadata order):
//  d_in[0] x          int32  [B, N, 2]
//  d_in[1] d          float  [B, 16]
//  d_in[2] gridWeight float  [16777216, 4]
//  d_in[3] W0         float  [22, 8]
//  d_in[4] W1         float  [8, 3]
// Output: sigma [B, N] then rgb [B, 3], concatenated, float32.
//
// Model (R1-R13): uint8 table (64MB, L2-resident after convert's
// write-allocate) + constant weights + warp-per-ray. surf sits at its
// MIO/L1tex wavefront floor (~300 MIO ops/warp ~= 50us); convert sits at
// its 320MB streaming floor (~40us). R14 recovers the serial glue via PDL:
// surf launches while convert runs, streams its indices + computes the
// per-ray base, then cudaGridDependencySynchronize() gates the gathers on
// convert completion (memory visibility guaranteed).

__device__ unsigned int g_q[TABLE];     // 64 MB: 4 x uint8 per row

__constant__ float cW0[22 * HID];       // raw W0 [22,8] row-major
__constant__ float cW1[HID * 3];        // raw W1 [8,3]  row-major

#define MAGIC_U  0x4B000000u            // float bits of 8388608.0f
#define MAGIC_F  8388608.f
#define INV65025 (1.f / 65025.f)
#define INV255   (1.f / 255.f)

// ---------------- Kernel A: fp32 -> uint8 table quantization ----------------
__device__ __forceinline__ unsigned int pack_row(float4 v) {
    unsigned int a = __float2uint_rn(v.x * 255.f);
    unsigned int b = __float2uint_rn(v.y * 255.f);
    unsigned int c = __float2uint_rn(v.z * 255.f);
    unsigned int d = __float2uint_rn(v.w * 255.f);
    return a | (b << 8) | (c << 16) | (d << 24);
}

__global__ __launch_bounds__(256) void convert_kernel(const float4* __restrict__ grid) {
    // allow the dependent surf kernel to begin its prologue early
    cudaTriggerProgrammaticLaunchCompletion();

    const int t    = blockIdx.x * blockDim.x + threadIdx.x;   // TABLE/4 threads
    const int base = t * 4;
    const float4 r0 = __ldcs(grid + base);
    const float4 r1 = __ldcs(grid + base + 1);
    const float4 r2 = __ldcs(grid + base + 2);
    const float4 r3 = __ldcs(grid + base + 3);
    uint4 o;
    o.x = pack_row(r0);
    o.y = pack_row(r1);
    o.z = pack_row(r2);
    o.w = pack_row(r3);
    *(((uint4*)g_q) + t) = o;   // normal store: write-allocate keeps table in L2
}

// ---------------- Kernel B: warp-per-ray gather + MLP + scan + reduce ----------------
__global__ __launch_bounds__(128) void surf_kernel(
    const uint4* __restrict__ x4,       // x as uint4 (4 ints = 2 sample pairs)
    const float* __restrict__ d,        // [B,16]
    float* __restrict__ out_sigma,      // [B,N]
    float* __restrict__ out_rgb)        // [B,3]
{
    const int ray  = blockIdx.x * 4 + (threadIdx.x >> 5);
    const int lane = threadIdx.x & 31;

    // ======== PROLOGUE: independent of the converted table ========
    // indices: samples lane*4 .. lane*4+3 -> 8 ints = 2 x LDG.128, coalesced
    const uint4* xp = x4 + (size_t)ray * (NS * 2 / 4) + lane * 2;
    const uint4 xa = __ldcs(xp);
    const uint4 xb = __ldcs(xp + 1);

    // per-ray base = 255 * (d-row @ W0[0:16]); lane computes j=lane&7
    float basev = 0.f;
    {
        const int j = lane & 7;
        const float4* dd = (const float4*)(d + (size_t)ray * IN_DIR);
        #pragma unroll
        for (int k4 = 0; k4 < 4; ++k4) {
            const float4 dv = __ldg(dd + k4);
            basev = fmaf(dv.x, cW0[(k4 * 4 + 0) * HID + j], basev);
            basev = fmaf(dv.y, cW0[(k4 * 4 + 1) * HID + j], basev);
            basev = fmaf(dv.z, cW0[(k4 * 4 + 2) * HID + j], basev);
            basev = fmaf(dv.w, cW0[(k4 * 4 + 3) * HID + j], basev);
        }
        basev *= 255.f;     // layer0 runs on raw bytes; /255 folded into sigmoid arg
    }
    float base[HID];
    #pragma unroll
    for (int j = 0; j < HID; ++j)
        base[j] = __shfl_sync(0xffffffffu, basev, j);

    // ======== gate: converted table must be fully written & visible ========
    cudaGridDependencySynchronize();

    // ---- 8 independent gathers, issued back-to-back (L2-resident table) ----
    unsigned int q0[4], q1[4];
    q0[0] = __ldcg(&g_q[xa.x]);  q1[0] = __ldcg(&g_q[xa.y]);
    q0[1] = __ldcg(&g_q[xa.z]);  q1[1] = __ldcg(&g_q[xa.w]);
    q0[2] = __ldcg(&g_q[xb.x]);  q1[2] = __ldcg(&g_q[xb.y]);
    q0[3] = __ldcg(&g_q[xb.z]);  q1[3] = __ldcg(&g_q[xb.w]);

    // ---- per-sample: sigma + tiny MLP ----
    float sig[4], cr[4], cg[4], cb[4];
    #pragma unroll
    for (int k = 0; k < 4; ++k) {
        const unsigned int a = q0[k], b = q1[k];

        // sigma: prod+MAGIC via one IMAD; one FMA gives -z; fast sigmoid
        const unsigned int pm = (a & 255u) * (b & 255u) + MAGIC_U;
        const float fp   = __uint_as_float(pm);                  // 8388608 + prod
        const float zneg = fmaf(fp, -INV65025, MAGIC_F * INV65025);
        sig[k] = __fdividef(1.f, 1.f + __expf(zneg));

        // geo bytes as exact small floats: PRMT + FSUB (no cvt, no scale)
        const float g0y = __uint_as_float(__byte_perm(a, MAGIC_U, 0x7441)) - MAGIC_F;
        const float g0z = __uint_as_float(__byte_perm(a, MAGIC_U, 0x7442)) - MAGIC_F;
        const float g0w = __uint_as_float(__byte_perm(a, MAGIC_U, 0x7443)) - MAGIC_F;
        const float g1y = __uint_as_float(__byte_perm(b, MAGIC_U, 0x7441)) - MAGIC_F;
        const float g1z = __uint_as_float(__byte_perm(b, MAGIC_U, 0x7442)) - MAGIC_F;
        const float g1w = __uint_as_float(__byte_perm(b, MAGIC_U, 0x7443)) - MAGIC_F;

        float h[HID];
        #pragma unroll
        for (int j = 0; j < HID; ++j) {
            float acc = base[j];
            acc = fmaf(g0y, cW0[(16 + 0) * HID + j], acc);
            acc = fmaf(g0z, cW0[(16 + 1) * HID + j], acc);
            acc = fmaf(g0w, cW0[(16 + 2) * HID + j], acc);
            acc = fmaf(g1y, cW0[(16 + 3) * HID + j], acc);
            acc = fmaf(g1z, cW0[(16 + 4) * HID + j], acc);
            acc = fmaf(g1w, cW0[(16 + 5) * HID + j], acc);
            h[j] = fmaxf(acc, 0.f);     // = 255 * true hidden
        }
        float c0 = 0.f, c1 = 0.f, c2 = 0.f;
        #pragma unroll
        for (int j = 0; j < HID; ++j) {
            c0 = fmaf(h[j], cW1[j * 3 + 0], c0);
            c1 = fmaf(h[j], cW1[j * 3 + 1], c1);
            c2 = fmaf(h[j], cW1[j * 3 + 2], c2);
        }
        // /255 folded here (scale of h) — one FMUL per channel
        cr[k] = __fdividef(1.f, 1.f + __expf(-c0 * INV255));
        cg[k] = __fdividef(1.f, 1.f + __expf(-c1 * INV255));
        cb[k] = __fdividef(1.f, 1.f + __expf(-c2 * INV255));
    }

    // ---- sigma out: one coalesced STG.128 per thread ----
    float4 s4 = make_float4(sig[0], sig[1], sig[2], sig[3]);
    __stcs((float4*)(out_sigma + (size_t)ray * NS) + lane, s4);

    // ---- exclusive prefix product of (1-sigma): local x warp-scan ----
    const float p0 = 1.f - sig[0];
    const float p1 = 1.f - sig[1];
    const float p2 = 1.f - sig[2];
    const float p3 = 1.f - sig[3];
    const float l1 = p0 * p1;            // local inclusive prefixes
    const float l2 = l1 * p2;
    const float ltot = l2 * p3;

    float incl = ltot;                   // warp inclusive scan of thread totals
    #pragma unroll
    for (int off = 1; off < 32; off <<= 1) {
        float v = __shfl_up_sync(0xffffffffu, incl, off);
        if (lane >= off) incl *= v;
    }
    float excl = __shfl_up_sync(0xffffffffu, incl, 1);   // exclusive
    if (lane == 0) excl = 1.f;

    const float w0 = excl      * sig[0];
    const float w1 = excl * p0 * sig[1];
    const float w2 = excl * l1 * sig[2];
    const float w3 = excl * l2 * sig[3];

    // ---- rgb = sum w*c : local accumulate then one warp butterfly ----
    float r = fmaf(w3, cr[3], fmaf(w2, cr[2], fmaf(w1, cr[1], w0 * cr[0])));
    float g = fmaf(w3, cg[3], fmaf(w2, cg[2], fmaf(w1, cg[1], w0 * cg[0])));
    float bl= fmaf(w3, cb[3], fmaf(w2, cb[2], fmaf(w1, cb[1], w0 * cb[0])));
    #pragma unroll
    for (int off = 16; off > 0; off >>= 1) {
        r  += __shfl_down_sync(0xffffffffu, r,  off);
        g  += __shfl_down_sync(0xffffffffu, g,  off);
        bl += __shfl_down_sync(0xffffffffu, bl, off);
    }
    if (lane == 0) {
        float* o = out_rgb + (size_t)ray * 3;
        o[0] = r; o[1] = g; o[2] = bl;
    }
}

extern "C" void kernel_launch(void* const* d_in, const int* in_sizes, int n_in,
                              void* d_out, int out_size) {
    const uint4* x4   = (const uint4*)d_in[0];
    const float* d    = (const float*)d_in[1];
    const float4* gw  = (const float4*)d_in[2];
    float* out_sigma  = (float*)d_out;
    float* out_rgb    = out_sigma + (size_t)RAYS * NS;

    // weights -> constant bank (D2D async memcpy: graph-capturable, no alloc);
    // issued first so they complete before surf's early prologue needs cW0.
    cudaMemcpyToSymbolAsync(cW0, d_in[3], 22 * HID * sizeof(float), 0,
                            cudaMemcpyDeviceToDevice);
    cudaMemcpyToSymbolAsync(cW1, d_in[4], HID * 3 * sizeof(float), 0,
                            cudaMemcpyDeviceToDevice);

    convert_kernel<<<TABLE / 4 / 256, 256>>>(gw);

    // surf with Programmatic Dependent Launch: prologue overlaps convert
    cudaLaunchConfig_t cfg = {};
    cfg.gridDim  = dim3(RAYS / 4, 1, 1);
    cfg.blockDim = dim3(128, 1, 1);
    cudaLaunchAttribute attrs[1];
    attrs[0].id = cudaLaunchAttributeProgrammaticStreamSerialization;
    attrs[0].val.programmaticStreamSerializationAllowed = 1;
    cfg.attrs = attrs;
    cfg.numAttrs = 1;
    cudaLaunchKernelEx(&cfg, surf_kernel, x4, d, out_sigma, out_rgb);
}